// round 7
// baseline (speedup 1.0000x reference)
#include <cuda_runtime.h>
#include <math.h>

#define BATCH 2
#define HH 512
#define WW 512
#define NC 21
#define PH 128
#define PW 128
#define KS 11
#define K2 121
#define PPLANE (PH*PW)

// -------- scratch (device globals; no allocation allowed) --------
__device__ float g_unary[BATCH*NC*HH*WW];   // 44 MB
__device__ float g_rgbp [BATCH*3*PPLANE];
__device__ float g_wkern[BATCH*K2*PPLANE];  // 15.9 MB combined pairwise kernel
__device__ float g_Qb   [BATCH*NC*PPLANE];
__device__ float g_msg  [BATCH*NC*PPLANE];

// ---- packed f32x2 helpers (sm_103a) ----
__device__ __forceinline__ unsigned long long pk2(float a, float b) {
    unsigned long long r;
    asm("mov.b64 %0, {%1, %2};" : "=l"(r) : "f"(a), "f"(b));
    return r;
}
__device__ __forceinline__ unsigned long long fma2(unsigned long long a,
                                                   unsigned long long b,
                                                   unsigned long long c) {
    unsigned long long d;
    asm("fma.rn.f32x2 %0, %1, %2, %3;" : "=l"(d) : "l"(a), "l"(b), "l"(c));
    return d;
}
__device__ __forceinline__ void upk2(unsigned long long v, float& lo, float& hi) {
    asm("mov.b64 {%0, %1}, %2;" : "=f"(lo), "=f"(hi) : "l"(v));
}

// -------- 3x3 conv backbone, 2 px/thread via packed f32x2 FMA --------
__global__ __launch_bounds__(256) void k_unary(const float* __restrict__ x,
                                               const float* __restrict__ w,
                                               const float* __restrict__ bias)
{
    __shared__ __align__(16) float2 sw2[NC][27];
    __shared__ float sb[NC];
    for (int i = threadIdx.x; i < NC*27; i += 256) {
        float wv = w[i];
        sw2[i/27][i%27] = make_float2(wv, wv);
    }
    if (threadIdx.x < NC) sb[threadIdx.x] = bias[threadIdx.x];
    __syncthreads();

    int idx = blockIdx.x*256 + threadIdx.x;
    if (idx >= BATCH*HH*(WW/2)) return;
    int x2 = idx & 255;            // WW/2 = 256
    int y  = (idx >> 8) & 511;
    int b  = idx >> 17;
    int xc = x2*2;

    float f[3][3][4];
#pragma unroll
    for (int ci = 0; ci < 3; ci++)
#pragma unroll
        for (int r = 0; r < 3; r++) {
            int yy = y + r - 1;
            bool yok = ((unsigned)yy < (unsigned)HH);
            const float* row = &x[((b*3 + ci)*HH + yy)*WW];
#pragma unroll
            for (int k = 0; k < 4; k++) {
                int xx = xc - 1 + k;
                f[ci][r][k] = (yok && (unsigned)xx < (unsigned)WW) ? __ldg(&row[xx]) : 0.f;
            }
        }
    unsigned long long P[27];
#pragma unroll
    for (int ci = 0; ci < 3; ci++)
#pragma unroll
        for (int r = 0; r < 3; r++)
#pragma unroll
            for (int kx = 0; kx < 3; kx++)
                P[(ci*3 + r)*3 + kx] = pk2(f[ci][r][kx], f[ci][r][kx+1]);

#pragma unroll
    for (int o = 0; o < NC; o++) {
        unsigned long long acc = pk2(sb[o], sb[o]);
        const float2* wrow = sw2[o];
#pragma unroll
        for (int j = 0; j < 27; j++) {
            float2 wp = wrow[j];
            acc = fma2(P[j], pk2(wp.x, wp.y), acc);
        }
        float lo, hi; upk2(acc, lo, hi);
        *reinterpret_cast<float2*>(&g_unary[((b*NC + o)*HH + y)*WW + xc]) = make_float2(lo, hi);
    }
}

// -------- pooled rgb features: avgpool4(x)/13 (float4 rows) --------
__global__ __launch_bounds__(256) void k_poolrgb(const float* __restrict__ x)
{
    int idx = blockIdx.x*256 + threadIdx.x;
    if (idx >= BATCH*3*PPLANE) return;
    int pw_ = idx % PW;
    int ph_ = (idx / PW) % PH;
    int c   = (idx / PPLANE) % 3;
    int b   = idx / (PPLANE*3);
    float s = 0.f;
#pragma unroll
    for (int r = 0; r < 4; r++) {
        float4 v = *reinterpret_cast<const float4*>(&x[((b*3 + c)*HH + ph_*4 + r)*WW + pw_*4]);
        s += (v.x + v.y) + (v.z + v.w);
    }
    g_rgbp[idx] = s * (1.f/16.f) * (1.f/13.f);
}

// -------- combined pairwise kernel: thread per (b, ky, pixel), __expf --------
__global__ __launch_bounds__(256) void k_wkern(const float* __restrict__ pwts)
{
    int idx = blockIdx.x*256 + threadIdx.x;
    if (idx >= BATCH*KS*PPLANE) return;
    int b   = idx / (KS*PPLANE);
    int rem = idx % (KS*PPLANE);
    int ky  = rem / PPLANE;
    int pix = rem % PPLANE;
    int pw_ = pix & 127, ph_ = pix >> 7;

    float p0 = __ldg(&pwts[0]), p1 = __ldg(&pwts[1]);
    float cy = 4.f*ph_ + 1.5f, cx = 4.f*pw_ + 1.5f;
    float cb0 = cy*(1.f/80.f), cb1 = cx*(1.f/80.f);
    float cs0 = cy*(1.f/3.f),  cs1 = cx*(1.f/3.f);

    const float* rp = &g_rgbp[(b*3)*PPLANE];
    float cr = __ldg(&rp[pix]);
    float cg = __ldg(&rp[PPLANE + pix]);
    float cB = __ldg(&rp[2*PPLANE + pix]);

    int ny = ph_ + ky - 5;
    bool yok = ((unsigned)ny < (unsigned)PH);
    float* wout = &g_wkern[(b*K2 + ky*KS)*PPLANE + pix];
#pragma unroll
    for (int kx = 0; kx < KS; kx++) {
        int nx = pw_ + kx - 5;
        float db0, db1, db2, db3, db4, ds0, ds1;
        if (yok && (unsigned)nx < (unsigned)PW) {
            float nyf = 4.f*ny + 1.5f, nxf = 4.f*nx + 1.5f;
            db0 = (nyf - cy)*(1.f/80.f);
            db1 = (nxf - cx)*(1.f/80.f);
            db2 = __ldg(&rp[ny*PW + nx]) - cr;
            db3 = __ldg(&rp[PPLANE + ny*PW + nx]) - cg;
            db4 = __ldg(&rp[2*PPLANE + ny*PW + nx]) - cB;
            ds0 = (nyf - cy)*(1.f/3.f);
            ds1 = (nxf - cx)*(1.f/3.f);
        } else {
            db0 = -cb0; db1 = -cb1; db2 = -cr; db3 = -cg; db4 = -cB;
            ds0 = -cs0; ds1 = -cs1;
        }
        float kb = __expf(-0.5f*(db0*db0 + db1*db1 + db2*db2 + db3*db3 + db4*db4));
        float ks = __expf(-0.5f*(ds0*ds0 + ds1*ds1));
        wout[kx*PPLANE] = p0*kb + p1*ks;
    }
}

// -------- fused: logQ = (use_msg ? uw*unary + up4(msg) : unary); Qb = pool4(softmax(logQ)) --------
__global__ __launch_bounds__(128) void k_softpool(const float* __restrict__ uw_p, int use_msg)
{
    int b    = blockIdx.z;
    int pr   = blockIdx.y;
    int tile = blockIdx.x;
    int tid  = threadIdx.x;
    int xc   = tile*128 + tid;
    float uw = __ldg(uw_p);

    float srcX = (xc + 0.5f)*0.25f - 0.5f;
    srcX = fminf(fmaxf(srcX, 0.f), 127.f);
    int   x0 = (int)floorf(srcX);
    int   x1 = min(x0 + 1, 127);
    float wx = srcX - (float)x0;

    float acc[NC];
#pragma unroll
    for (int c = 0; c < NC; c++) acc[c] = 0.f;

    for (int iy = 0; iy < 4; iy++) {
        int y = pr*4 + iy;
        float l[NC];
        if (!use_msg) {
#pragma unroll
            for (int c = 0; c < NC; c++)
                l[c] = __ldg(&g_unary[((b*NC + c)*HH + y)*WW + xc]);
        } else {
            float srcY = (y + 0.5f)*0.25f - 0.5f;
            srcY = fminf(fmaxf(srcY, 0.f), 127.f);
            int   y0 = (int)floorf(srcY);
            int   y1 = min(y0 + 1, 127);
            float wy = srcY - (float)y0;
            float w00 = (1.f - wy)*(1.f - wx), w01 = (1.f - wy)*wx;
            float w10 = wy*(1.f - wx),         w11 = wy*wx;
#pragma unroll
            for (int c = 0; c < NC; c++) {
                const float* mp = &g_msg[(b*NC + c)*PPLANE];
                float m = w00*__ldg(&mp[y0*PW + x0]) + w01*__ldg(&mp[y0*PW + x1])
                        + w10*__ldg(&mp[y1*PW + x0]) + w11*__ldg(&mp[y1*PW + x1]);
                l[c] = uw*__ldg(&g_unary[((b*NC + c)*HH + y)*WW + xc]) + m;
            }
        }
        float mx = l[0];
#pragma unroll
        for (int c = 1; c < NC; c++) mx = fmaxf(mx, l[c]);
        float s = 0.f;
#pragma unroll
        for (int c = 0; c < NC; c++) { l[c] = __expf(l[c] - mx); s += l[c]; }
        float inv = 1.f / s;
#pragma unroll
        for (int c = 0; c < NC; c++) acc[c] += l[c]*inv;
    }
#pragma unroll
    for (int c = 0; c < NC; c++) {
        float v = acc[c];
        v += __shfl_down_sync(0xffffffffu, v, 1);
        v += __shfl_down_sync(0xffffffffu, v, 2);
        acc[c] = v;
    }
    if ((tid & 3) == 0) {
        int pc = tile*32 + (tid >> 2);
#pragma unroll
        for (int c = 0; c < NC; c++)
            g_Qb[((b*NC + c)*PH + pr)*PW + pc] = acc[c]*(1.f/16.f);
    }
}

// -------- PAC message v2: 32x8 tile, warp = 2 adjacent out rows, all 21 channels --------
// smem: all channels, rows 8+10, cols 32+10. grid (4, 16, B), 128 threads.
#define SQ_ROWS 18
#define SQ_COLS 42
#define SQ_PLANE (SQ_ROWS*SQ_COLS)
__global__ __launch_bounds__(128) void k_pac()
{
    extern __shared__ float sQ[];          // [NC][18][42] = 63504 B
    int b    = blockIdx.z;
    int ty0  = blockIdx.y * 8;
    int tx0  = blockIdx.x * 32;
    int tid  = threadIdx.x;
    int lane = tid & 31;
    int wrp  = tid >> 5;

    for (int i = tid; i < NC*SQ_PLANE; i += 128) {
        int col = i % SQ_COLS;
        int r   = (i / SQ_COLS) % SQ_ROWS;
        int c   = i / SQ_PLANE;
        int gy = ty0 + r - 5, gx = tx0 + col - 5;
        float v = 0.f;
        if ((unsigned)gy < (unsigned)PH && (unsigned)gx < (unsigned)PW)
            v = __ldg(&g_Qb[((b*NC + c)*PH + gy)*PW + gx]);
        sQ[i] = v;
    }
    __syncthreads();

    int r0   = wrp*2;                      // out rows r0, r0+1 within tile
    int ph0  = ty0 + r0;
    int pix0 = ph0*PW + tx0 + lane;
    const float* wk = &g_wkern[b*K2*PPLANE];

    float acc0[NC], acc1[NC];
#pragma unroll
    for (int c = 0; c < NC; c++) { acc0[c] = 0.f; acc1[c] = 0.f; }

    // input row i serves out0 with ky=i (i<=10) and out1 with ky=i-1 (i>=1)
    for (int i = 0; i < 12; i++) {
        const float* srow = &sQ[(r0 + i)*SQ_COLS + lane];
#pragma unroll
        for (int kx = 0; kx < KS; kx++) {
            float w0 = (i <= 10) ? __ldg(&wk[(i*KS + kx)*PPLANE + pix0])       : 0.f;
            float w1 = (i >= 1)  ? __ldg(&wk[((i-1)*KS + kx)*PPLANE + pix0 + PW]) : 0.f;
#pragma unroll
            for (int c = 0; c < NC; c++) {
                float v = srow[c*SQ_PLANE + kx];
                acc0[c] += w0*v;
                acc1[c] += w1*v;
            }
        }
    }
#pragma unroll
    for (int c = 0; c < NC; c++) {
        g_msg[(b*NC + c)*PPLANE + pix0]      = acc0[c];
        g_msg[(b*NC + c)*PPLANE + pix0 + PW] = acc1[c];
    }
}

// -------- final: out = uw*unary + up4(msg) --------
__global__ __launch_bounds__(256) void k_final(const float* __restrict__ uw_p,
                                               float* __restrict__ out)
{
    int i = blockIdx.x*256 + threadIdx.x;
    if (i >= BATCH*NC*HH*WW) return;
    int x  = i & (WW - 1);
    int y  = (i >> 9) & (HH - 1);
    int bc = i >> 18;
    float uw = __ldg(uw_p);

    float srcY = (y + 0.5f)*0.25f - 0.5f;
    srcY = fminf(fmaxf(srcY, 0.f), 127.f);
    int   y0 = (int)floorf(srcY);
    int   y1 = min(y0 + 1, 127);
    float wy = srcY - (float)y0;

    float srcX = (x + 0.5f)*0.25f - 0.5f;
    srcX = fminf(fmaxf(srcX, 0.f), 127.f);
    int   x0 = (int)floorf(srcX);
    int   x1 = min(x0 + 1, 127);
    float wx = srcX - (float)x0;

    const float* mp = &g_msg[bc*PPLANE];
    float m = (1.f - wy)*((1.f - wx)*__ldg(&mp[y0*PW + x0]) + wx*__ldg(&mp[y0*PW + x1]))
            +        wy *((1.f - wx)*__ldg(&mp[y1*PW + x0]) + wx*__ldg(&mp[y1*PW + x1]));
    out[i] = uw*__ldg(&g_unary[i]) + m;
}

extern "C" void kernel_launch(void* const* d_in, const int* in_sizes, int n_in,
                              void* d_out, int out_size)
{
    const float* x    = (const float*)d_in[0];
    const float* w    = (const float*)d_in[1];
    const float* bias = (const float*)d_in[2];
    const float* uw   = (const float*)d_in[3];
    const float* pwts = (const float*)d_in[4];
    float* out = (float*)d_out;
    (void)in_sizes; (void)n_in; (void)out_size;

    const int pacSmem = NC*SQ_PLANE*(int)sizeof(float);   // 63504 B
    cudaFuncSetAttribute(k_pac, cudaFuncAttributeMaxDynamicSharedMemorySize, pacSmem);

    k_unary  <<<(BATCH*HH*(WW/2) + 255)/256, 256>>>(x, w, bias);
    k_poolrgb<<<(BATCH*3*PPLANE + 255)/256, 256>>>(x);
    k_wkern  <<<(BATCH*KS*PPLANE + 255)/256, 256>>>(pwts);

    dim3 gSoft(4, PH, BATCH);
    dim3 gPac (PW/32, PH/8, BATCH);

    k_softpool<<<gSoft, 128>>>(uw, 0);
    for (int t = 0; t < 5; t++) {
        k_pac<<<gPac, 128, pacSmem>>>();
        if (t < 4) k_softpool<<<gSoft, 128>>>(uw, 1);
        else       k_final<<<(BATCH*NC*HH*WW + 255)/256, 256>>>(uw, out);
    }
}